// round 3
// baseline (speedup 1.0000x reference)
#include <cuda_runtime.h>
#include <cuda_bf16.h>
#include <cstdint>

#define BSZ 32
#define LEN 8192
#define NPF 256          // output feature dim
#define SEGLEN 512
#define INTMX 0x7fffffff

// Per-(row, eighth) partial first-valid index. Always fully written each run.
__device__ int g_part[BSZ * 8];

// ---------------------------------------------------------------------------
// Kernel A: partial first-valid scan. Grid (8, BSZ) x 256 threads.
// Block (p, b) scans mask[b, p*1024 .. p*1024+1023] (1 int4 per thread) and
// writes the min valid index (or INTMX) to g_part[b*8+p].
// ---------------------------------------------------------------------------
__global__ void __launch_bounds__(256) start_kernel(const int* __restrict__ mask) {
    const int b = blockIdx.y, p = blockIdx.x;
    const int tid = threadIdx.x;
    const int base = p * 1024 + tid * 4;
    int4 v = ((const int4*)(mask + (size_t)b * LEN))[p * 256 + tid];

    int fv = INTMX;
    if (v.w) fv = base + 3;
    if (v.z) fv = base + 2;
    if (v.y) fv = base + 1;
    if (v.x) fv = base + 0;

    const int lane = tid & 31, wid = tid >> 5;
#pragma unroll
    for (int o = 16; o; o >>= 1) fv = min(fv, __shfl_xor_sync(0xffffffffu, fv, o));

    __shared__ int wmin[8];
    if (lane == 0) wmin[wid] = fv;
    __syncthreads();
    if (tid < 32) {
        int mn = (lane < 8) ? wmin[lane] : INTMX;
#pragma unroll
        for (int o = 4; o; o >>= 1) mn = min(mn, __shfl_xor_sync(0xffffffffu, mn, o));
        if (lane == 0) g_part[b * 8 + p] = mn;
    }
}

// ---------------------------------------------------------------------------
// Kernel B: embedding + fill, fused. Grid (17, BSZ), 512 threads.
//   seg 0..15 : segment [start+seg*512, +512). 8 chunks of 64 i-positions;
//               chunk = tid>>6 (0..7), j = tid&63 -> feature pairs 2j, 2j+1.
//   seg 16    : prefix fill [0, start) with (0,1,0,1,...) (whole row if no
//               valid position).
// ---------------------------------------------------------------------------
__global__ void __launch_bounds__(512) embed_kernel(const int* __restrict__ mask,
                                                    float* __restrict__ out) {
    const int b = blockIdx.y;
    const int seg = blockIdx.x;
    const int tid = threadIdx.x;

    // reconstruct first-valid index from the 8 partials (uniform loads)
    int start = INTMX;
#pragma unroll
    for (int p = 0; p < 8; ++p) start = min(start, g_part[b * 8 + p]);
    const int valid = (start != INTMX);
    if (!valid) start = 0;

    if (seg == 16) {
        const int fill_end = valid ? start : LEN;
        if (fill_end == 0) return;
        const float4 pat = make_float4(0.0f, 1.0f, 0.0f, 1.0f);
        float4* o = (float4*)(out + (size_t)b * LEN * NPF);
        const int total = fill_end * (NPF / 4);
        for (int t = tid; t < total; t += 512) o[t] = pat;
        return;
    }

    if (!valid) return;
    const int i0 = start + seg * SEGLEN;
    if (i0 >= LEN) return;
    const int i1 = min(i0 + SEGLEN, LEN);
    const int nseg = i1 - i0;

    __shared__ int sm[SEGLEN];
    __shared__ int part[8];
    const int* mrow = mask + (size_t)b * LEN;
    {
        const int t = tid;  // 512 threads, 512 elements: one each
        sm[t] = (t < nseg) ? mrow[i0 + t] : 0;
    }
    __syncthreads();

    // per-64-chunk mask counts: warp w (w<8) reduces sm[w*64 .. w*64+63]
    if (tid < 256) {
        const int w = tid >> 5, lane = tid & 31;
        int s = sm[w * 64 + lane * 2 + 0] + sm[w * 64 + lane * 2 + 1];
#pragma unroll
        for (int o = 16; o; o >>= 1) s += __shfl_xor_sync(0xffffffffu, s, o);
        if (lane == 0) part[w] = s;
    }
    __syncthreads();

    const int chunk = tid >> 6;       // 0..7
    const int j = tid & 63;
    const int ia = i0 + chunk * 64;
    if (ia >= i1) return;
    const int ib = min(ia + 64, i1);

    int m0 = 0, n = 0;
#pragma unroll
    for (int w = 0; w < 8; ++w) {
        n += part[w];
        if (w < chunk) m0 += part[w];
    }
    const float base = 6.283185307179586f / ((float)n + 1e-6f);

    // per-thread rotation deltas for feature pairs 2j, 2j+1
    const float K2 = 0.10381025296523007f;  // log2(10000)/128
    const float d0 = base * exp2f(-(float)(2 * j) * K2);
    const float d1 = base * exp2f(-(float)(2 * j + 1) * K2);

    float s0, c0, s1, c1, sd0, cd0, sd1, cd1;
    __sincosf((float)m0 * d0, &s0, &c0);
    __sincosf((float)m0 * d1, &s1, &c1);
    __sincosf(d0, &sd0, &cd0);
    __sincosf(d1, &sd1, &cd1);

    float4* op = (float4*)(out + (size_t)(b * LEN + ia) * NPF) + j;
    const int* smc = sm + (ia - i0);
    const int cnt = ib - ia;
#pragma unroll 4
    for (int i = 0; i < cnt; ++i, op += NPF / 4) {
        if (smc[i]) {  // warp-uniform: all lanes in a warp share chunk/i
            float ns0 = fmaf(s0, cd0, c0 * sd0);
            float nc0 = fmaf(c0, cd0, -s0 * sd0);
            float ns1 = fmaf(s1, cd1, c1 * sd1);
            float nc1 = fmaf(c1, cd1, -s1 * sd1);
            s0 = ns0; c0 = nc0; s1 = ns1; c1 = nc1;
        }
        *op = make_float4(s0, c0, s1, c1);
    }
}

extern "C" void kernel_launch(void* const* d_in, const int* in_sizes, int n_in,
                              void* d_out, int out_size) {
    (void)in_sizes; (void)n_in; (void)out_size;
    const int* mask = (const int*)d_in[1];   // inputs: x (unused), mask
    float* out = (float*)d_out;

    start_kernel<<<dim3(8, BSZ), 256>>>(mask);
    embed_kernel<<<dim3(17, BSZ), 512>>>(mask, out);
}

// round 4
// speedup vs baseline: 1.0309x; 1.0309x over previous
#include <cuda_runtime.h>
#include <cuda_bf16.h>
#include <cstdint>

#define BSZ 32
#define LEN 8192
#define NPF 256          // output feature dim
#define SEGLEN 512
#define INTMX 0x7fffffff

// ---------------------------------------------------------------------------
// Single fused kernel. Grid (17, BSZ), 512 threads.
// Phase 1 (all blocks): block-local scan of row b's mask -> first-valid index.
//   (17 blocks per row; row mask is 32KB, stays L2-resident across the row's
//   blocks, so DRAM cost ~1MB total.)
// Phase 2:
//   seg 0..15 : segment [start+seg*512, +512). 16 warps = 16 chunks of 32
//               i-positions. Lane j handles float4 cols j and j+32 (feature
//               pairs 2j,2j+1 and 2j+64,2j+65): two independent rotation
//               streams + two independent 16B stores per step.
//   seg 16    : prefix fill [0, start) with (0,1,0,1,...) (whole row if the
//               row has no valid position).
// ---------------------------------------------------------------------------
__global__ void __launch_bounds__(512) embed_kernel(const int* __restrict__ mask,
                                                    float* __restrict__ out) {
    const int b = blockIdx.y;
    const int seg = blockIdx.x;
    const int tid = threadIdx.x;
    const int lane = tid & 31;
    const int w = tid >> 5;           // warp id = chunk id (0..15)

    const int* __restrict__ mrow = mask + (size_t)b * LEN;

    __shared__ int red[16];
    __shared__ int s_part[16];
    __shared__ int s_start;

    // ---- Phase 1: first-valid index of row b ----
    int fv = INTMX;
    const int4* m4 = (const int4*)mrow;
#pragma unroll
    for (int q = 0; q < 4; ++q) {
        const int idx = tid + q * 512;     // int4 index 0..2047
        const int4 v = m4[idx];
        const int base = idx * 4;
        if (v.x) fv = min(fv, base + 0);
        if (v.y) fv = min(fv, base + 1);
        if (v.z) fv = min(fv, base + 2);
        if (v.w) fv = min(fv, base + 3);
    }
#pragma unroll
    for (int o = 16; o; o >>= 1) fv = min(fv, __shfl_xor_sync(0xffffffffu, fv, o));
    if (lane == 0) red[w] = fv;
    __syncthreads();
    if (tid < 32) {
        int mn = (lane < 16) ? red[lane] : INTMX;
#pragma unroll
        for (int o = 8; o; o >>= 1) mn = min(mn, __shfl_xor_sync(0xffffffffu, mn, o));
        if (lane == 0) s_start = mn;
    }
    __syncthreads();

    const int raw = s_start;
    const int valid = (raw != INTMX);
    const int start = valid ? raw : 0;

    // ---- seg 16: prefix / invalid-row fill ----
    if (seg == 16) {
        const int fill_end = valid ? start : LEN;
        if (fill_end == 0) return;
        const float4 pat = make_float4(0.0f, 1.0f, 0.0f, 1.0f);
        float4* o = (float4*)(out + (size_t)b * LEN * NPF);
        const int total = fill_end * (NPF / 4);
        for (int t = tid; t < total; t += 512) __stcs(o + t, pat);
        return;
    }
    if (!valid) return;

    const int i0 = start + seg * SEGLEN;
    const int i1 = min(i0 + SEGLEN, LEN);

    // ---- per-chunk mask bits via ballot; counts via popc ----
    const int pos = i0 + tid;                 // warp w covers [i0+w*32, +32)
    const int mv = (i0 < LEN && pos < i1) ? mrow[pos] : 0;
    const unsigned bits = __ballot_sync(0xffffffffu, mv != 0);
    if (lane == 0) s_part[w] = __popc(bits);
    __syncthreads();

    if (i0 >= LEN) return;

    int m0 = 0, n = 0;
#pragma unroll
    for (int q = 0; q < 16; ++q) {
        const int pq = s_part[q];
        n += pq;
        if (q < w) m0 += pq;
    }

    const int ia = i0 + w * 32;
    if (ia >= i1) return;
    const int cnt = min(32, i1 - ia);

    const float base = 6.283185307179586f / ((float)n + 1e-6f);

    // deltas: lane j -> feature pairs (2j, 2j+1) and (2j+64, 2j+65)
    const float K2 = 0.10381025296523007f;    // log2(10000)/128
    const int j = lane;
    const float d0 = base * exp2f(-(float)(2 * j) * K2);
    const float d1 = base * exp2f(-(float)(2 * j + 1) * K2);
    const float d2 = d0 * 0.01f;              // 10000^(-64/128) = 1/100
    const float d3 = d1 * 0.01f;

    float s0, c0, s1, c1, s2, c2, s3, c3;
    float sd0, cd0, sd1, cd1, sd2, cd2, sd3, cd3;
    const float fm0 = (float)m0;
    __sincosf(fm0 * d0, &s0, &c0);
    __sincosf(fm0 * d1, &s1, &c1);
    __sincosf(fm0 * d2, &s2, &c2);
    __sincosf(fm0 * d3, &s3, &c3);
    __sincosf(d0, &sd0, &cd0);
    __sincosf(d1, &sd1, &cd1);
    __sincosf(d2, &sd2, &cd2);
    __sincosf(d3, &sd3, &cd3);

    float4* op0 = (float4*)(out + (size_t)(b * LEN + ia) * NPF) + j;
    float4* op1 = op0 + 32;
#pragma unroll 4
    for (int i = 0; i < cnt; ++i, op0 += NPF / 4, op1 += NPF / 4) {
        if ((bits >> i) & 1u) {               // warp-uniform
            float t;
            t = fmaf(s0, cd0, c0 * sd0); c0 = fmaf(c0, cd0, -s0 * sd0); s0 = t;
            t = fmaf(s1, cd1, c1 * sd1); c1 = fmaf(c1, cd1, -s1 * sd1); s1 = t;
            t = fmaf(s2, cd2, c2 * sd2); c2 = fmaf(c2, cd2, -s2 * sd2); s2 = t;
            t = fmaf(s3, cd3, c3 * sd3); c3 = fmaf(c3, cd3, -s3 * sd3); s3 = t;
        }
        __stcs(op0, make_float4(s0, c0, s1, c1));
        __stcs(op1, make_float4(s2, c2, s3, c3));
    }
}

extern "C" void kernel_launch(void* const* d_in, const int* in_sizes, int n_in,
                              void* d_out, int out_size) {
    (void)in_sizes; (void)n_in; (void)out_size;
    const int* mask = (const int*)d_in[1];   // inputs: x (unused), mask
    float* out = (float*)d_out;

    embed_kernel<<<dim3(17, BSZ), 512>>>(mask, out);
}

// round 5
// speedup vs baseline: 1.1144x; 1.0809x over previous
#include <cuda_runtime.h>
#include <cuda_bf16.h>
#include <cstdint>

#define BSZ 32
#define LEN 8192
#define NPF 256          // output feature dim
#define INTMX 0x7fffffff

// ---------------------------------------------------------------------------
// Single fused kernel, fine-grained for wave balance.
// Grid (129, BSZ), 64 threads (2 warps). Block (b, u):
//   u < u0  : embedding for i in [start + u*64, +64). seg = u>>3.
//             Warp w covers 32 i-positions; lane j handles float4 cols j and
//             j+32 (feature pairs 2j,2j+1 and 2j+64,2j+65).
//   u >= u0 : fill worker f=u-u0 writes [f*64, +64) of the (0,1,0,1,...)
//             prefix region [0, start) (whole row when no valid position).
// u0 = ceil((LEN-start)/64); blocks with u>=u0 would start past LEN anyway.
// ---------------------------------------------------------------------------
__global__ void __launch_bounds__(64) embed_kernel(const int* __restrict__ mask,
                                                   float* __restrict__ out) {
    const int b = blockIdx.y;
    const int u = blockIdx.x;          // 0..128
    const int tid = threadIdx.x;       // 0..63
    const int lane = tid & 31;
    const int w = tid >> 5;            // 0 or 1

    const int* __restrict__ mrow = mask + (size_t)b * LEN;

    __shared__ int s_start;
    __shared__ unsigned s_bits[16];

    // ---- Phase 1: first-valid index (warp 0, progressive strip scan) ----
    if (w == 0) {
        int res = INTMX;
        for (int k = 0; k < LEN / 32; ++k) {
            const int v = mrow[k * 32 + lane];
            const unsigned bal = __ballot_sync(0xffffffffu, v != 0);
            if (bal) { res = k * 32 + (__ffs(bal) - 1); break; }
        }
        if (lane == 0) s_start = res;
    }
    __syncthreads();

    const int raw = s_start;
    const int valid = (raw != INTMX);
    const int start = valid ? raw : 0;
    const int fill_end = valid ? start : LEN;
    const int u0 = valid ? ((LEN - start + 63) >> 6) : 0;

    // ---- fill workers (blocks whose embed range would start past LEN) ----
    if (u >= u0) {
        const int fa = (u - u0) * 64;
        if (fa >= fill_end) return;
        const int fb = min(fa + 64, fill_end);
        const float4 pat = make_float4(0.0f, 1.0f, 0.0f, 1.0f);
        float4* o = (float4*)(out + (size_t)(b * LEN + fa) * NPF);
        const int total = (fb - fa) * (NPF / 4);
        for (int t = tid; t < total; t += 64) __stcs(o + t, pat);
        return;
    }

    // ---- embedding block ----
    const int seg = u >> 3;
    const int i0 = start + seg * 512;        // segment start
    const int i1 = min(i0 + 512, LEN);       // segment end (exclusive)

    // ballots over the full 512-wide segment window (8 strips of 64)
#pragma unroll
    for (int s = 0; s < 8; ++s) {
        const int pos = i0 + s * 64 + tid;
        const int v = (pos < LEN) ? mrow[pos] : 0;
        const unsigned bal = __ballot_sync(0xffffffffu, v != 0);
        if (lane == 0) s_bits[s * 2 + w] = bal;
    }
    __syncthreads();

    const int myidx = (u & 7) * 2 + w;       // this warp's 32-chunk in segment
    int m0 = 0, n = 0;
#pragma unroll
    for (int q = 0; q < 16; ++q) {
        const int pq = __popc(s_bits[q]);
        n += pq;
        if (q < myidx) m0 += pq;
    }
    const unsigned bits = s_bits[myidx];

    const int iw = start + u * 64 + w * 32;  // this warp's first i
    if (iw >= i1) return;
    const int cnt = min(32, i1 - iw);

    const float base = 6.283185307179586f / ((float)n + 1e-6f);

    // deltas: lane j -> feature pairs (2j, 2j+1) and (2j+64, 2j+65)
    const float K2 = 0.10381025296523007f;   // log2(10000)/128
    const int j = lane;
    const float d0 = base * exp2f(-(float)(2 * j) * K2);
    const float d1 = base * exp2f(-(float)(2 * j + 1) * K2);
    const float d2 = d0 * 0.01f;             // 10000^(-64/128) = 1/100
    const float d3 = d1 * 0.01f;

    float s0, c0, s1, c1, s2, c2, s3, c3;
    float sd0, cd0, sd1, cd1, sd2, cd2, sd3, cd3;
    const float fm0 = (float)m0;             // m0*base <= 2*pi always
    __sincosf(fm0 * d0, &s0, &c0);
    __sincosf(fm0 * d1, &s1, &c1);
    __sincosf(fm0 * d2, &s2, &c2);
    __sincosf(fm0 * d3, &s3, &c3);
    __sincosf(d0, &sd0, &cd0);
    __sincosf(d1, &sd1, &cd1);
    __sincosf(d2, &sd2, &cd2);
    __sincosf(d3, &sd3, &cd3);

    float4* op0 = (float4*)(out + (size_t)(b * LEN + iw) * NPF) + j;
    float4* op1 = op0 + 32;
#pragma unroll 4
    for (int i = 0; i < cnt; ++i, op0 += NPF / 4, op1 += NPF / 4) {
        if ((bits >> i) & 1u) {              // warp-uniform
            float t;
            t = fmaf(s0, cd0, c0 * sd0); c0 = fmaf(c0, cd0, -s0 * sd0); s0 = t;
            t = fmaf(s1, cd1, c1 * sd1); c1 = fmaf(c1, cd1, -s1 * sd1); s1 = t;
            t = fmaf(s2, cd2, c2 * sd2); c2 = fmaf(c2, cd2, -s2 * sd2); s2 = t;
            t = fmaf(s3, cd3, c3 * sd3); c3 = fmaf(c3, cd3, -s3 * sd3); s3 = t;
        }
        __stcs(op0, make_float4(s0, c0, s1, c1));
        __stcs(op1, make_float4(s2, c2, s3, c3));
    }
}

extern "C" void kernel_launch(void* const* d_in, const int* in_sizes, int n_in,
                              void* d_out, int out_size) {
    (void)in_sizes; (void)n_in; (void)out_size;
    const int* mask = (const int*)d_in[1];   // inputs: x (unused), mask
    float* out = (float*)d_out;

    embed_kernel<<<dim3(129, BSZ), 64>>>(mask, out);
}